// round 2
// baseline (speedup 1.0000x reference)
#include <cuda_runtime.h>
#include <cstdint>
#include <cstddef>

#define NROWS 65536
#define DIM   128
#define DHALF 64
#define KCB   2048

// main kernel tiling
#define TM 128            // rows per block
#define TN 128            // codes per chunk
#define MAIN_THREADS 256
#define SMEM_MAIN (DHALF*2*TM*4 + DHALF*TN*4 + TM*4)   // sA(dup) + sB + sArg = 98816 B

// ---------------- device scratch (no allocation allowed) ----------------
__device__ float g_zt[DHALF * NROWS];   // z_^T        [d][r]
__device__ float g_et[DHALF * KCB];     // -2*emb_^T   [d][j]
__device__ float g_c [KCB];             // ||emb_j||^2

// ---------------- packed fp32x2 helpers ----------------
union U2 { unsigned long long u; float2 f; };

__device__ __forceinline__ void fma2(unsigned long long &acc,
                                     unsigned long long a,
                                     unsigned long long b) {
    asm("fma.rn.f32x2 %0, %1, %2, %0;" : "+l"(acc) : "l"(a), "l"(b));
}

// one 16B shared load -> two packed 64-bit (float pair) registers
__device__ __forceinline__ void lds_p2(const float* p,
                                       unsigned long long &x,
                                       unsigned long long &y) {
    unsigned a = (unsigned)__cvta_generic_to_shared(p);
    asm volatile("ld.shared.v2.u64 {%0, %1}, [%2];" : "=l"(x), "=l"(y) : "r"(a));
}

// ---------------- projection kernel: out = X @ W^T + b ----------------
// X [M][128] -> transposed output [64][M]; for embeddings also writes -2*val and c.
__global__ __launch_bounds__(128) void proj_kernel(
    const float* __restrict__ X,
    const float* __restrict__ Wm,     // [64][128]
    const float* __restrict__ bias,   // [64]
    int isEmb)
{
    __shared__ float sW[DIM][DHALF + 4];   // [k][d], padded row (272B, 16B aligned)
    int tid = threadIdx.x;
    #pragma unroll 4
    for (int i = tid; i < DIM * DHALF; i += 128) {
        int d = i >> 7, k = i & 127;
        sW[k][d] = Wm[i];                  // Wm[d*128+k]
    }
    __syncthreads();

    int r = blockIdx.x * 128 + tid;
    float acc[DHALF];
    #pragma unroll
    for (int d = 0; d < DHALF; d++) acc[d] = __ldg(&bias[d]);

    const float* xr = X + (size_t)r * DIM;
    #pragma unroll 1
    for (int kc = 0; kc < DIM; kc += 16) {
        float xv[16];
        #pragma unroll
        for (int j = 0; j < 16; j++) xv[j] = __ldg(&xr[kc + j]);
        #pragma unroll
        for (int j = 0; j < 16; j++) {
            float a = xv[j];
            #pragma unroll
            for (int d4 = 0; d4 < DHALF/4; d4++) {
                float4 w = *(const float4*)&sW[kc + j][d4*4];
                acc[d4*4+0] = fmaf(a, w.x, acc[d4*4+0]);
                acc[d4*4+1] = fmaf(a, w.y, acc[d4*4+1]);
                acc[d4*4+2] = fmaf(a, w.z, acc[d4*4+2]);
                acc[d4*4+3] = fmaf(a, w.w, acc[d4*4+3]);
            }
        }
    }

    if (isEmb) {
        float c = 0.f;
        #pragma unroll
        for (int d = 0; d < DHALF; d++) c = fmaf(acc[d], acc[d], c);
        g_c[r] = c;
        #pragma unroll
        for (int d = 0; d < DHALF; d++) g_et[d * KCB + r] = -2.f * acc[d];
    } else {
        #pragma unroll
        for (int d = 0; d < DHALF; d++) g_zt[d * NROWS + r] = acc[d];
    }
}

// ---------------- fused score GEMM + argmin + outputs ----------------
// score(r,j) = ||emb_j||^2 - 2 * dot(z_r, emb_j)  =  g_c[j] + dot(g_zt[:,r], g_et[:,j])
__global__ __launch_bounds__(MAIN_THREADS, 2) void vq_main_kernel(
    const float* __restrict__ emb,    // original embeddings [K][128] (for gather)
    float* __restrict__ out)
{
    extern __shared__ float smem[];
    float* sA   = smem;                                 // [64][2*TM]  z_^T duplicated (64KB)
    float* sB   = smem + DHALF * 2 * TM;                // [64][TN]    -2*emb_^T chunk (32KB)
    int*   sArg = (int*)(smem + DHALF * 2 * TM + DHALF * TN);

    int tid = threadIdx.x;
    int tc  = tid & 15;          // code group: codes tc*8 .. tc*8+7 of the chunk
    int tr  = tid >> 4;          // row group:  rows  tr*8 .. tr*8+7 of the tile
    int row0 = blockIdx.x * TM;

    // load z_^T tile, duplicating each value so ld.shared.v2.u64 yields (a,a) pairs
    for (int i = tid; i < DHALF * TM; i += MAIN_THREADS) {
        int k = i >> 7, r = i & 127;
        float v = g_zt[k * NROWS + row0 + r];
        sA[k * (2*TM) + 2*r]     = v;
        sA[k * (2*TM) + 2*r + 1] = v;
    }

    float bv[8];
    int   bi[8];
    #pragma unroll
    for (int i = 0; i < 8; i++) { bv[i] = 3.4e38f; bi[i] = 0; }

    for (int ch = 0; ch < KCB; ch += TN) {
        __syncthreads();
        for (int i = tid; i < DHALF * TN; i += MAIN_THREADS) {
            int k = i >> 7, c = i & 127;
            sB[k * TN + c] = g_et[k * KCB + ch + c];
        }
        __syncthreads();

        float4 c0 = *(const float4*)&g_c[ch + tc*8];
        float4 c1 = *(const float4*)&g_c[ch + tc*8 + 4];

        unsigned long long acc[8][4];
        #pragma unroll
        for (int r = 0; r < 8; r++)
            #pragma unroll
            for (int j = 0; j < 4; j++) acc[r][j] = 0ULL;

        #pragma unroll 8
        for (int k = 0; k < DHALF; k++) {
            unsigned long long a[8], b[4];
            const float* pa = &sA[k * (2*TM) + tr * 16];
            const float* pb = &sB[k * TN + tc * 8];
            lds_p2(pa,      a[0], a[1]);
            lds_p2(pa + 4,  a[2], a[3]);
            lds_p2(pa + 8,  a[4], a[5]);
            lds_p2(pa + 12, a[6], a[7]);
            lds_p2(pb,      b[0], b[1]);
            lds_p2(pb + 4,  b[2], b[3]);
            #pragma unroll
            for (int r = 0; r < 8; r++)
                #pragma unroll
                for (int j = 0; j < 4; j++)
                    fma2(acc[r][j], a[r], b[j]);
        }

        float cc[8] = {c0.x, c0.y, c0.z, c0.w, c1.x, c1.y, c1.z, c1.w};
        #pragma unroll
        for (int r = 0; r < 8; r++) {
            #pragma unroll
            for (int j = 0; j < 4; j++) {
                U2 u; u.u = acc[r][j];
                float s0 = u.f.x + cc[2*j];
                float s1 = u.f.y + cc[2*j+1];
                int   i0 = ch + tc*8 + 2*j;
                if (s0 < bv[r]) { bv[r] = s0; bi[r] = i0;     }
                if (s1 < bv[r]) { bv[r] = s1; bi[r] = i0 + 1; }
            }
        }
    }

    // reduce argmin across the 16 code-group lanes (lane bits 0..3 == tc)
    #pragma unroll
    for (int off = 1; off < 16; off <<= 1) {
        #pragma unroll
        for (int r = 0; r < 8; r++) {
            float ov = __shfl_xor_sync(0xffffffffu, bv[r], off);
            int   oi = __shfl_xor_sync(0xffffffffu, bi[r], off);
            if (ov < bv[r] || (ov == bv[r] && oi < bi[r])) { bv[r] = ov; bi[r] = oi; }
        }
    }
    __syncthreads();   // done reading sA/sB; sArg may alias later epilogue reads
    if (tc == 0) {
        #pragma unroll
        for (int i = 0; i < 8; i++) sArg[tr * 8 + i] = bi[i];
    }
    __syncthreads();

    float* outQ = out;                               // quantized [N][128]
    float* outH = out + (size_t)NROWS * DIM;         // one_hot   [N][2048]

    // quantized: gather original embeddings rows (float4, coalesced)
    for (int i = tid; i < TM * 32; i += MAIN_THREADS) {
        int r = i >> 5, s = i & 31;
        int a = sArg[r];
        float4 v = *(const float4*)&emb[(size_t)a * DIM + s * 4];
        *(float4*)&outQ[(size_t)(row0 + r) * DIM + s * 4] = v;
    }

    // one_hot: write zeros with the single 1.0 inserted (float4, coalesced)
    for (int i = tid; i < TM * 512; i += MAIN_THREADS) {
        int r = i >> 9, q = i & 511;
        int a = sArg[r];
        float4 v = make_float4(0.f, 0.f, 0.f, 0.f);
        if ((a >> 2) == q) ((float*)&v)[a & 3] = 1.0f;
        *(float4*)&outH[(size_t)(row0 + r) * KCB + (size_t)q * 4] = v;
    }
}

// ---------------- launch ----------------
extern "C" void kernel_launch(void* const* d_in, const int* in_sizes, int n_in,
                              void* d_out, int out_size) {
    const float* z   = (const float*)d_in[0];   // [65536][128]
    const float* W   = (const float*)d_in[1];   // [64][128]
    const float* b   = (const float*)d_in[2];   // [64]
    const float* emb = (const float*)d_in[3];   // [2048][128]
    float* out = (float*)d_out;

    // projections (z and codebook) into half-dim transposed layouts + norms
    proj_kernel<<<NROWS / 128, 128>>>(z,   W, b, 0);
    proj_kernel<<<KCB   / 128, 128>>>(emb, W, b, 1);

    // fused distance GEMM + argmin + one_hot/quantized epilogue
    cudaFuncSetAttribute(vq_main_kernel,
                         cudaFuncAttributeMaxDynamicSharedMemorySize, SMEM_MAIN);
    vq_main_kernel<<<NROWS / TM, MAIN_THREADS, SMEM_MAIN>>>(emb, out);
}